// round 16
// baseline (speedup 1.0000x reference)
#include <cuda_runtime.h>
#include <cuda_bf16.h>
#include <math_constants.h>
#include <cstdint>

#define DDIM    512
#define N_ROWS  16384
#define K_CODES 8192

// ---- GEMM tiling ----
#define BM      128
#define BN      256
#define BKH     64            // halves per chunk = full 128B rows
#define NCHUNK  (DDIM / BKH)  // 8
#define NTILE   (K_CODES / BN) // 32
#define ROWSTR_B 144          // 64 halves + 8 pad -> stride 9 (16B units), conflict-free
#define STAGE_B ((BM + BN) * ROWSTR_B)   // 55296
#define NSTAGE  4
#define SMEM_GEMM (NSTAGE * STAGE_B)     // 221184

#define MAXCAND 64

// ---- device scratch (allocation-free) ----
__device__ __nv_bfloat16 g_xb[(size_t)N_ROWS * DDIM];
__device__ __nv_bfloat16 g_eb[(size_t)K_CODES * DDIM];
__device__ __align__(16) float g_bias[K_CODES];        // -0.5*||e||^2
__device__ float g_xnorm[N_ROWS];
__device__ int   g_emax2;                               // max ||e||^2 (float bits); idempotent
__device__ __nv_bfloat162 g_sc2[(size_t)N_ROWS * (K_CODES / 2)];  // scores WITH bias folded
__device__ uint32_t g_tilemax[(size_t)N_ROWS * NTILE];  // fenc(per-row per-tile fp32 max)

// ---------------------------------------------------------------------------
__device__ __forceinline__ uint32_t smem_u32(const void* p) {
    uint32_t a;
    asm("{ .reg .u64 t; cvta.to.shared.u64 t, %1; cvt.u32.u64 %0, t; }" : "=r"(a) : "l"(p));
    return a;
}
__device__ __forceinline__ void cp16(uint32_t dst, const void* src) {
    asm volatile("cp.async.cg.shared.global [%0], [%1], 16;" :: "r"(dst), "l"(src) : "memory");
}
#define CP_COMMIT() asm volatile("cp.async.commit_group;" ::: "memory")
#define CP_WAIT1()  asm volatile("cp.async.wait_group 1;" ::: "memory")

__device__ __forceinline__ void ldsm4(uint32_t* r, uint32_t addr) {
    asm volatile("ldmatrix.sync.aligned.m8n8.x4.shared.b16 {%0,%1,%2,%3}, [%4];"
                 : "=r"(r[0]), "=r"(r[1]), "=r"(r[2]), "=r"(r[3]) : "r"(addr));
}
__device__ __forceinline__ void mma_bf16(float* d, const uint32_t* a, const uint32_t* b) {
    asm volatile(
        "mma.sync.aligned.m16n8k16.row.col.f32.bf16.bf16.f32 "
        "{%0,%1,%2,%3}, {%4,%5,%6,%7}, {%8,%9}, {%0,%1,%2,%3};"
        : "+f"(d[0]), "+f"(d[1]), "+f"(d[2]), "+f"(d[3])
        : "r"(a[0]), "r"(a[1]), "r"(a[2]), "r"(a[3]), "r"(b[0]), "r"(b[1]));
}

// order-preserving float<->uint for atomicMax
__device__ __forceinline__ uint32_t fenc(float f) {
    uint32_t u = __float_as_uint(f);
    return (u & 0x80000000u) ? ~u : (u | 0x80000000u);
}
__device__ __forceinline__ float fdec(uint32_t u) {
    return __uint_as_float((u & 0x80000000u) ? (u ^ 0x80000000u) : ~u);
}

// ---------------------------------------------------------------------------
// conv: merged x+e conversion.  Warp w < N_ROWS -> x row; else e row.
// ---------------------------------------------------------------------------
__global__ void conv_kernel(const float* __restrict__ x, const float* __restrict__ e) {
    int w = (blockIdx.x * blockDim.x + threadIdx.x) >> 5;
    int lane = threadIdx.x & 31;
    if (w < N_ROWS) {
        const int row = w;
        const float4* src = reinterpret_cast<const float4*>(x + (size_t)row * DDIM);
        uint4* dst = reinterpret_cast<uint4*>(g_xb + (size_t)row * DDIM);
        float s = 0.f;
#pragma unroll
        for (int j = 0; j < 2; j++) {
            __nv_bfloat162 h[4];
            float4 v0 = src[lane * 4 + j * 2];
            float4 v1 = src[lane * 4 + j * 2 + 1];
            s += v0.x*v0.x + v0.y*v0.y + v0.z*v0.z + v0.w*v0.w;
            s += v1.x*v1.x + v1.y*v1.y + v1.z*v1.z + v1.w*v1.w;
            h[0] = __nv_bfloat162(__float2bfloat16_rn(v0.x), __float2bfloat16_rn(v0.y));
            h[1] = __nv_bfloat162(__float2bfloat16_rn(v0.z), __float2bfloat16_rn(v0.w));
            h[2] = __nv_bfloat162(__float2bfloat16_rn(v1.x), __float2bfloat16_rn(v1.y));
            h[3] = __nv_bfloat162(__float2bfloat16_rn(v1.z), __float2bfloat16_rn(v1.w));
            dst[lane * 2 + j] = *reinterpret_cast<uint4*>(h);
        }
        g_tilemax[(size_t)row * NTILE + lane] = 0u;   // 0 == fenc(-inf); graph-replay safe
#pragma unroll
        for (int off = 16; off; off >>= 1) s += __shfl_xor_sync(0xFFFFFFFFu, s, off);
        if (lane == 0) g_xnorm[row] = sqrtf(s);
    } else if (w < N_ROWS + K_CODES) {
        const int row = w - N_ROWS;
        const float4* src = reinterpret_cast<const float4*>(e + (size_t)row * DDIM);
        uint4* dst = reinterpret_cast<uint4*>(g_eb + (size_t)row * DDIM);
        float s = 0.f;
#pragma unroll
        for (int j = 0; j < 2; j++) {
            __nv_bfloat162 h[4];
            float4 v0 = src[lane * 4 + j * 2];
            float4 v1 = src[lane * 4 + j * 2 + 1];
            s += v0.x*v0.x + v0.y*v0.y + v0.z*v0.z + v0.w*v0.w;
            s += v1.x*v1.x + v1.y*v1.y + v1.z*v1.z + v1.w*v1.w;
            h[0] = __nv_bfloat162(__float2bfloat16_rn(v0.x), __float2bfloat16_rn(v0.y));
            h[1] = __nv_bfloat162(__float2bfloat16_rn(v0.z), __float2bfloat16_rn(v0.w));
            h[2] = __nv_bfloat162(__float2bfloat16_rn(v1.x), __float2bfloat16_rn(v1.y));
            h[3] = __nv_bfloat162(__float2bfloat16_rn(v1.z), __float2bfloat16_rn(v1.w));
            dst[lane * 2 + j] = *reinterpret_cast<uint4*>(h);
        }
#pragma unroll
        for (int off = 16; off; off >>= 1) s += __shfl_xor_sync(0xFFFFFFFFu, s, off);
        if (lane == 0) {
            g_bias[row] = -0.5f * s;
            atomicMax(&g_emax2, __float_as_int(s));
        }
    }
}

// ---------------------------------------------------------------------------
// GEMM: 4-stage ring, barrier every other chunk, register-double-buffered
// ldmatrix fragments (prefetch step s+1 during step s's MMAs).
// ---------------------------------------------------------------------------
extern __shared__ char smem_g[];

__device__ __forceinline__ void gemm_issue(uint32_t smb, int stage, int row0, int col0,
                                           int chunk, int tid) {
    const int d0 = chunk * BKH;
    const uint32_t st = smb + stage * STAGE_B;
#pragma unroll
    for (int it = 0; it < 12; it++) {              // 384 rows x 8 x 16B / 256 thr
        int i = tid + it * 256;
        int r = i >> 3, c = i & 7;
        if (r < BM) {
            cp16(st + r * ROWSTR_B + c * 16, g_xb + (size_t)(row0 + r) * DDIM + d0 + c * 8);
        } else {
            int r2 = r - BM;
            cp16(st + BM * ROWSTR_B + r2 * ROWSTR_B + c * 16,
                 g_eb + (size_t)(col0 + r2) * DDIM + d0 + c * 8);
        }
    }
}

__global__ __launch_bounds__(256, 1) void gemm_kernel() {
    const int tid = threadIdx.x;
    const int lane = tid & 31;
    const int wid = tid >> 5;
    const int wm = wid >> 2;
    const int wn = wid & 3;
    const int g = lane >> 2;
    const int q = lane & 3;
    const int col0 = blockIdx.x * BN;
    const int row0 = blockIdx.y * BM;
    const uint32_t smb = smem_u32(smem_g);

    const int a_row = wm * 64 + (lane & 15);
    const int a_col = (lane >> 4) << 4;
    const int b_row = wn * 64 + (lane & 7) + ((lane & 16) ? 8 : 0);
    const int b_col = (lane & 8) ? 16 : 0;

    float acc[4][8][4];
#pragma unroll
    for (int mt = 0; mt < 4; mt++)
#pragma unroll
        for (int nt = 0; nt < 8; nt++)
#pragma unroll
            for (int c = 0; c < 4; c++) acc[mt][nt][c] = 0.f;

    gemm_issue(smb, 0, row0, col0, 0, tid); CP_COMMIT();
    gemm_issue(smb, 1, row0, col0, 1, tid); CP_COMMIT();

    for (int ch = 0; ch < NCHUNK; ch++) {
        CP_WAIT1();                      // chunk ch resident (outstanding: ch+1)
        // 4-stage ring: stage (ch+2)%4 was last READ at iter ch-2 -> barrier
        // every second chunk orders reads before overwrites.
        if ((ch & 1) == 0) __syncthreads();

        const bool pf = (ch + 2 < NCHUNK);
        const int  pfd0 = (ch + 2) * BKH;
        const uint32_t pst = smb + ((ch + 2) % NSTAGE) * STAGE_B;

        const uint32_t sa_b = smb + (ch % NSTAGE) * STAGE_B;
        const uint32_t sb_b = sa_b + BM * ROWSTR_B;
        const uint32_t a_base = sa_b + a_row * ROWSTR_B + a_col;
        const uint32_t b_base = sb_b + b_row * ROWSTR_B + b_col;

        uint32_t afrag[2][4][4], bfrag[2][4][4];
        // preload k-step 0 fragments
#pragma unroll
        for (int mt = 0; mt < 4; mt++)
            ldsm4(afrag[0][mt], a_base + mt * (16 * ROWSTR_B));
#pragma unroll
        for (int ntp = 0; ntp < 4; ntp++)
            ldsm4(bfrag[0][ntp], b_base + ntp * (16 * ROWSTR_B));

#pragma unroll
        for (int s = 0; s < 4; s++) {    // four k16 steps per 128B chunk
            const int cb = s & 1;
            const int nb = cb ^ 1;
            // prefetch next step's fragments into the alternate buffer
            if (s < 3) {
                const int sc32 = (s + 1) * 32;
#pragma unroll
                for (int mt = 0; mt < 4; mt++)
                    ldsm4(afrag[nb][mt], a_base + mt * (16 * ROWSTR_B) + sc32);
#pragma unroll
                for (int ntp = 0; ntp < 4; ntp++)
                    ldsm4(bfrag[nb][ntp], b_base + ntp * (16 * ROWSTR_B) + sc32);
            }
            if (pf) {                    // 3 of 12 chunk-prefetch cp16 per step
#pragma unroll
                for (int j = 0; j < 3; j++) {
                    int i = tid + (s * 3 + j) * 256;
                    int r = i >> 3, c = i & 7;
                    if (r < BM) {
                        cp16(pst + r * ROWSTR_B + c * 16,
                             g_xb + (size_t)(row0 + r) * DDIM + pfd0 + c * 8);
                    } else {
                        int r2 = r - BM;
                        cp16(pst + BM * ROWSTR_B + r2 * ROWSTR_B + c * 16,
                             g_eb + (size_t)(col0 + r2) * DDIM + pfd0 + c * 8);
                    }
                }
            }
#pragma unroll
            for (int mt = 0; mt < 4; mt++)
#pragma unroll
                for (int ntp = 0; ntp < 4; ntp++) {
                    mma_bf16(acc[mt][2 * ntp],     afrag[cb][mt], &bfrag[cb][ntp][0]);
                    mma_bf16(acc[mt][2 * ntp + 1], afrag[cb][mt], &bfrag[cb][ntp][2]);
                }
        }
        CP_COMMIT();                     // one group per chunk (possibly empty)
    }

    // epilogue: fold bias, store bf16 scores, per-row tile max sidecar
    float bc0[8], bc1[8];
#pragma unroll
    for (int nt = 0; nt < 8; nt++) {
        int c = col0 + wn * 64 + nt * 8 + q * 2;
        bc0[nt] = __ldg(&g_bias[c]);
        bc1[nt] = __ldg(&g_bias[c + 1]);
    }
#pragma unroll
    for (int mt = 0; mt < 4; mt++) {
        int r = row0 + wm * 64 + mt * 16 + g;
        float m1 = -CUDART_INF_F, m2 = -CUDART_INF_F;
#pragma unroll
        for (int nt = 0; nt < 8; nt++) {
            float v0 = acc[mt][nt][0] + bc0[nt];
            float v1 = acc[mt][nt][1] + bc1[nt];
            float v2 = acc[mt][nt][2] + bc0[nt];
            float v3 = acc[mt][nt][3] + bc1[nt];
            m1 = fmaxf(m1, fmaxf(v0, v1));
            m2 = fmaxf(m2, fmaxf(v2, v3));
            int c2 = (col0 >> 1) + wn * 32 + nt * 4 + q;
            g_sc2[(size_t)r * (K_CODES / 2) + c2] =
                __nv_bfloat162(__float2bfloat16_rn(v0), __float2bfloat16_rn(v1));
            g_sc2[(size_t)(r + 8) * (K_CODES / 2) + c2] =
                __nv_bfloat162(__float2bfloat16_rn(v2), __float2bfloat16_rn(v3));
        }
        m1 = fmaxf(m1, __shfl_xor_sync(0xFFFFFFFFu, m1, 1));
        m1 = fmaxf(m1, __shfl_xor_sync(0xFFFFFFFFu, m1, 2));
        m2 = fmaxf(m2, __shfl_xor_sync(0xFFFFFFFFu, m2, 1));
        m2 = fmaxf(m2, __shfl_xor_sync(0xFFFFFFFFu, m2, 2));
        if (q == 0) {
            atomicMax(&g_tilemax[(size_t)r * NTILE + blockIdx.x], fenc(m1));
            atomicMax(&g_tilemax[(size_t)(r + 8) * NTILE + blockIdx.x], fenc(m2));
        }
    }
}

// ---------------------------------------------------------------------------
// Select + gather: warp per row. tilemax -> ballot tiles -> candidate filter
// -> (n==1 shortcut) -> exact fp32 rescore -> output.
// ---------------------------------------------------------------------------
__global__ __launch_bounds__(256) void select_kernel(const float* __restrict__ x,
                                                     const float* __restrict__ embed,
                                                     float* __restrict__ out, int write_ind) {
    __shared__ int cnt[8];
    __shared__ int cands[8][MAXCAND];

    const int wrow = threadIdx.x >> 5;
    const int row = blockIdx.x * 8 + wrow;
    const int lane = threadIdx.x & 31;
    if (row >= N_ROWS) return;

    const uint32_t tenc = g_tilemax[(size_t)row * NTILE + lane];

    if (lane == 0) cnt[wrow] = 0;
    __syncwarp();

    const float4* x4 = reinterpret_cast<const float4*>(x + (size_t)row * DDIM);
    float4 xv[4];
#pragma unroll
    for (int j = 0; j < 4; j++) xv[j] = x4[lane + 32 * j];

    const float tv = fdec(tenc);
    float gmax = tv;
#pragma unroll
    for (int off = 16; off; off >>= 1) gmax = fmaxf(gmax, __shfl_xor_sync(0xFFFFFFFFu, gmax, off));

    const float margin = 0.02f * g_xnorm[row] * sqrtf(__int_as_float(g_emax2)) + 1.0f;
    const float thr = gmax - margin;

    unsigned tmask = __ballot_sync(0xFFFFFFFFu, tv >= thr);

    const uint4* s16 = reinterpret_cast<const uint4*>(g_sc2 + (size_t)row * (K_CODES / 2));

    while (tmask) {
        const int t = __ffs(tmask) - 1;
        tmask &= tmask - 1;
        uint4 u = s16[t * 32 + lane];
#pragma unroll
        for (int w = 0; w < 4; w++) {
            uint32_t uw = (&u.x)[w];
            float2 p = __bfloat1622float2(*reinterpret_cast<__nv_bfloat162*>(&uw));
            if (p.x >= thr) {
                int pos = atomicAdd(&cnt[wrow], 1);
                if (pos < MAXCAND) cands[wrow][pos] = t * 256 + lane * 8 + w * 2;
            }
            if (p.y >= thr) {
                int pos = atomicAdd(&cnt[wrow], 1);
                if (pos < MAXCAND) cands[wrow][pos] = t * 256 + lane * 8 + w * 2 + 1;
            }
        }
    }
    __syncwarp();
    const int n = cnt[wrow];

    float best = -CUDART_INF_F;
    int bi = K_CODES;

    if (n == 1) {
        bi = cands[wrow][0];             // sole survivor of a superset filter
    } else if (n <= MAXCAND) {
        for (int ci = 0; ci < n; ci++) {
            int k = cands[wrow][ci];
            const float4* e4 = reinterpret_cast<const float4*>(embed + (size_t)k * DDIM);
            float s = 0.f;
#pragma unroll
            for (int j = 0; j < 4; j++) {
                float4 ev = e4[lane + 32 * j];
                s += xv[j].x * ev.x + xv[j].y * ev.y + xv[j].z * ev.z + xv[j].w * ev.w;
            }
#pragma unroll
            for (int off = 16; off; off >>= 1) s += __shfl_xor_sync(0xFFFFFFFFu, s, off);
            float v = s + g_bias[k];
            if (v > best || (v == best && k < bi)) { best = v; bi = k; }
        }
    } else {
        for (int k = lane; k < K_CODES; k += 32) {
            const float4* e4 = reinterpret_cast<const float4*>(embed + (size_t)k * DDIM);
            float s = 0.f;
            for (int j = 0; j < DDIM / 4; j++) {
                float4 ev = e4[j];
                float4 xw = x4[j];
                s += xw.x * ev.x + xw.y * ev.y + xw.z * ev.z + xw.w * ev.w;
            }
            float v = s + g_bias[k];
            if (v > best || (v == best && k < bi)) { best = v; bi = k; }
        }
#pragma unroll
        for (int off = 16; off; off >>= 1) {
            float ov = __shfl_xor_sync(0xFFFFFFFFu, best, off);
            int   oi = __shfl_xor_sync(0xFFFFFFFFu, bi, off);
            if (ov > best || (ov == best && oi < bi)) { best = ov; bi = oi; }
        }
    }

    bi = __shfl_sync(0xFFFFFFFFu, bi, 0);

    const float4* src = reinterpret_cast<const float4*>(embed + (size_t)bi * DDIM);
    float4* dst = reinterpret_cast<float4*>(out + (size_t)row * DDIM);
#pragma unroll
    for (int j = 0; j < 4; j++) dst[lane + 32 * j] = src[lane + 32 * j];
    if (write_ind && lane == 0) out[(size_t)N_ROWS * DDIM + row] = (float)bi;
}

// ---------------------------------------------------------------------------
extern "C" void kernel_launch(void* const* d_in, const int* in_sizes, int n_in,
                              void* d_out, int out_size) {
    const float* x     = (const float*)d_in[0];
    const float* embed = (const float*)d_in[1];
    float* out = (float*)d_out;
    (void)in_sizes; (void)n_in;
    int write_ind = (out_size >= N_ROWS * DDIM + N_ROWS) ? 1 : 0;

    cudaFuncSetAttribute(gemm_kernel, cudaFuncAttributeMaxDynamicSharedMemorySize, SMEM_GEMM);

    conv_kernel<<<(N_ROWS + K_CODES) / 8, 256>>>(x, embed);
    gemm_kernel<<<dim3(K_CODES / BN, N_ROWS / BM), 256, SMEM_GEMM>>>();
    select_kernel<<<N_ROWS / 8, 256>>>(x, embed, out, write_ind);
}

// round 17
// speedup vs baseline: 1.0377x; 1.0377x over previous
#include <cuda_runtime.h>
#include <cuda_bf16.h>
#include <math_constants.h>
#include <cstdint>

#define DDIM    512
#define N_ROWS  16384
#define K_CODES 8192

// ---- GEMM tiling ----
#define BM      128
#define BN      256
#define BKH     64            // halves per chunk = full 128B rows
#define NCHUNK  (DDIM / BKH)  // 8
#define NTILE   (K_CODES / BN) // 32
#define ROWSTR_B 144          // 64 halves + 8 pad -> stride 9 (16B units), conflict-free
#define STAGE_B ((BM + BN) * ROWSTR_B)   // 55296
#define NSTAGE  4
#define SMEM_GEMM (NSTAGE * STAGE_B)     // 221184

#define MAXCAND 64

// ---- device scratch (allocation-free) ----
__device__ __nv_bfloat16 g_xb[(size_t)N_ROWS * DDIM];
__device__ __nv_bfloat16 g_eb[(size_t)K_CODES * DDIM];
__device__ __align__(16) float g_bias[K_CODES];        // -0.5*||e||^2
__device__ float g_xnorm[N_ROWS];
__device__ int   g_emax2;                               // max ||e||^2 (float bits); idempotent
__device__ uint32_t g_sc2[(size_t)N_ROWS * (K_CODES / 2)];  // packed bf162 scores (bias folded)
__device__ uint32_t g_tilemax[(size_t)N_ROWS * NTILE];  // fenc(per-row per-tile fp32 max)

// ---------------------------------------------------------------------------
__device__ __forceinline__ uint32_t smem_u32(const void* p) {
    uint32_t a;
    asm("{ .reg .u64 t; cvta.to.shared.u64 t, %1; cvt.u32.u64 %0, t; }" : "=r"(a) : "l"(p));
    return a;
}
__device__ __forceinline__ void cp16(uint32_t dst, const void* src) {
    asm volatile("cp.async.cg.shared.global [%0], [%1], 16;" :: "r"(dst), "l"(src) : "memory");
}
#define CP_COMMIT() asm volatile("cp.async.commit_group;" ::: "memory")
#define CP_WAIT1()  asm volatile("cp.async.wait_group 1;" ::: "memory")

__device__ __forceinline__ void ldsm4(uint32_t* r, uint32_t addr) {
    asm volatile("ldmatrix.sync.aligned.m8n8.x4.shared.b16 {%0,%1,%2,%3}, [%4];"
                 : "=r"(r[0]), "=r"(r[1]), "=r"(r[2]), "=r"(r[3]) : "r"(addr));
}
__device__ __forceinline__ void mma_bf16(float* d, const uint32_t* a, const uint32_t* b) {
    asm volatile(
        "mma.sync.aligned.m16n8k16.row.col.f32.bf16.bf16.f32 "
        "{%0,%1,%2,%3}, {%4,%5,%6,%7}, {%8,%9}, {%0,%1,%2,%3};"
        : "+f"(d[0]), "+f"(d[1]), "+f"(d[2]), "+f"(d[3])
        : "r"(a[0]), "r"(a[1]), "r"(a[2]), "r"(a[3]), "r"(b[0]), "r"(b[1]));
}

__device__ __forceinline__ uint32_t pack_bf2(float a, float b) {
    __nv_bfloat162 h(__float2bfloat16_rn(a), __float2bfloat16_rn(b));
    return *reinterpret_cast<uint32_t*>(&h);
}

// order-preserving float<->uint for atomicMax
__device__ __forceinline__ uint32_t fenc(float f) {
    uint32_t u = __float_as_uint(f);
    return (u & 0x80000000u) ? ~u : (u | 0x80000000u);
}
__device__ __forceinline__ float fdec(uint32_t u) {
    return __uint_as_float((u & 0x80000000u) ? (u ^ 0x80000000u) : ~u);
}

// ---------------------------------------------------------------------------
// conv: merged x+e conversion.  Warp w < N_ROWS -> x row; else e row.
// ---------------------------------------------------------------------------
__global__ void conv_kernel(const float* __restrict__ x, const float* __restrict__ e) {
    int w = (blockIdx.x * blockDim.x + threadIdx.x) >> 5;
    int lane = threadIdx.x & 31;
    if (w < N_ROWS) {
        const int row = w;
        const float4* src = reinterpret_cast<const float4*>(x + (size_t)row * DDIM);
        uint4* dst = reinterpret_cast<uint4*>(g_xb + (size_t)row * DDIM);
        float s = 0.f;
#pragma unroll
        for (int j = 0; j < 2; j++) {
            __nv_bfloat162 h[4];
            float4 v0 = src[lane * 4 + j * 2];
            float4 v1 = src[lane * 4 + j * 2 + 1];
            s += v0.x*v0.x + v0.y*v0.y + v0.z*v0.z + v0.w*v0.w;
            s += v1.x*v1.x + v1.y*v1.y + v1.z*v1.z + v1.w*v1.w;
            h[0] = __nv_bfloat162(__float2bfloat16_rn(v0.x), __float2bfloat16_rn(v0.y));
            h[1] = __nv_bfloat162(__float2bfloat16_rn(v0.z), __float2bfloat16_rn(v0.w));
            h[2] = __nv_bfloat162(__float2bfloat16_rn(v1.x), __float2bfloat16_rn(v1.y));
            h[3] = __nv_bfloat162(__float2bfloat16_rn(v1.z), __float2bfloat16_rn(v1.w));
            dst[lane * 2 + j] = *reinterpret_cast<uint4*>(h);
        }
        g_tilemax[(size_t)row * NTILE + lane] = 0u;   // 0 == fenc(-inf); graph-replay safe
#pragma unroll
        for (int off = 16; off; off >>= 1) s += __shfl_xor_sync(0xFFFFFFFFu, s, off);
        if (lane == 0) g_xnorm[row] = sqrtf(s);
    } else if (w < N_ROWS + K_CODES) {
        const int row = w - N_ROWS;
        const float4* src = reinterpret_cast<const float4*>(e + (size_t)row * DDIM);
        uint4* dst = reinterpret_cast<uint4*>(g_eb + (size_t)row * DDIM);
        float s = 0.f;
#pragma unroll
        for (int j = 0; j < 2; j++) {
            __nv_bfloat162 h[4];
            float4 v0 = src[lane * 4 + j * 2];
            float4 v1 = src[lane * 4 + j * 2 + 1];
            s += v0.x*v0.x + v0.y*v0.y + v0.z*v0.z + v0.w*v0.w;
            s += v1.x*v1.x + v1.y*v1.y + v1.z*v1.z + v1.w*v1.w;
            h[0] = __nv_bfloat162(__float2bfloat16_rn(v0.x), __float2bfloat16_rn(v0.y));
            h[1] = __nv_bfloat162(__float2bfloat16_rn(v0.z), __float2bfloat16_rn(v0.w));
            h[2] = __nv_bfloat162(__float2bfloat16_rn(v1.x), __float2bfloat16_rn(v1.y));
            h[3] = __nv_bfloat162(__float2bfloat16_rn(v1.z), __float2bfloat16_rn(v1.w));
            dst[lane * 2 + j] = *reinterpret_cast<uint4*>(h);
        }
#pragma unroll
        for (int off = 16; off; off >>= 1) s += __shfl_xor_sync(0xFFFFFFFFu, s, off);
        if (lane == 0) {
            g_bias[row] = -0.5f * s;
            atomicMax(&g_emax2, __float_as_int(s));
        }
    }
}

// ---------------------------------------------------------------------------
// GEMM: 4-stage ring, barrier every other chunk, cp.async spread over k-steps
// (504us-winner mainloop). Epilogue stores via .cs to protect L2 working set.
// ---------------------------------------------------------------------------
extern __shared__ char smem_g[];

__device__ __forceinline__ void gemm_issue(uint32_t smb, int stage, int row0, int col0,
                                           int chunk, int tid) {
    const int d0 = chunk * BKH;
    const uint32_t st = smb + stage * STAGE_B;
#pragma unroll
    for (int it = 0; it < 12; it++) {              // 384 rows x 8 x 16B / 256 thr
        int i = tid + it * 256;
        int r = i >> 3, c = i & 7;
        if (r < BM) {
            cp16(st + r * ROWSTR_B + c * 16, g_xb + (size_t)(row0 + r) * DDIM + d0 + c * 8);
        } else {
            int r2 = r - BM;
            cp16(st + BM * ROWSTR_B + r2 * ROWSTR_B + c * 16,
                 g_eb + (size_t)(col0 + r2) * DDIM + d0 + c * 8);
        }
    }
}

__global__ __launch_bounds__(256, 1) void gemm_kernel() {
    const int tid = threadIdx.x;
    const int lane = tid & 31;
    const int wid = tid >> 5;
    const int wm = wid >> 2;
    const int wn = wid & 3;
    const int g = lane >> 2;
    const int q = lane & 3;
    const int col0 = blockIdx.x * BN;
    const int row0 = blockIdx.y * BM;
    const uint32_t smb = smem_u32(smem_g);

    const int a_row = wm * 64 + (lane & 15);
    const int a_col = (lane >> 4) << 4;
    const int b_row = wn * 64 + (lane & 7) + ((lane & 16) ? 8 : 0);
    const int b_col = (lane & 8) ? 16 : 0;

    float acc[4][8][4];
#pragma unroll
    for (int mt = 0; mt < 4; mt++)
#pragma unroll
        for (int nt = 0; nt < 8; nt++)
#pragma unroll
            for (int c = 0; c < 4; c++) acc[mt][nt][c] = 0.f;

    gemm_issue(smb, 0, row0, col0, 0, tid); CP_COMMIT();
    gemm_issue(smb, 1, row0, col0, 1, tid); CP_COMMIT();

    for (int ch = 0; ch < NCHUNK; ch++) {
        CP_WAIT1();                      // chunk ch resident (outstanding: ch+1)
        // 4-stage ring: stage (ch+2)%4 was last READ at iter ch-2 -> barrier
        // every second chunk orders reads before overwrites.
        if ((ch & 1) == 0) __syncthreads();

        const bool pf = (ch + 2 < NCHUNK);
        const int  pfd0 = (ch + 2) * BKH;
        const uint32_t pst = smb + ((ch + 2) % NSTAGE) * STAGE_B;

        const uint32_t sa_b = smb + (ch % NSTAGE) * STAGE_B;
        const uint32_t sb_b = sa_b + BM * ROWSTR_B;
        const uint32_t a_base = sa_b + a_row * ROWSTR_B + a_col;
        const uint32_t b_base = sb_b + b_row * ROWSTR_B + b_col;

#pragma unroll
        for (int s = 0; s < 4; s++) {    // four k16 steps per 128B chunk
            if (pf) {                    // 3 of 12 prefetch cp16 per step
#pragma unroll
                for (int j = 0; j < 3; j++) {
                    int i = tid + (s * 3 + j) * 256;
                    int r = i >> 3, c = i & 7;
                    if (r < BM) {
                        cp16(pst + r * ROWSTR_B + c * 16,
                             g_xb + (size_t)(row0 + r) * DDIM + pfd0 + c * 8);
                    } else {
                        int r2 = r - BM;
                        cp16(pst + BM * ROWSTR_B + r2 * ROWSTR_B + c * 16,
                             g_eb + (size_t)(col0 + r2) * DDIM + pfd0 + c * 8);
                    }
                }
            }
            const int sc32 = s * 32;
            uint32_t a[4][4], b[4][4];
#pragma unroll
            for (int mt = 0; mt < 4; mt++)
                ldsm4(a[mt], a_base + mt * (16 * ROWSTR_B) + sc32);
#pragma unroll
            for (int ntp = 0; ntp < 4; ntp++)
                ldsm4(b[ntp], b_base + ntp * (16 * ROWSTR_B) + sc32);
#pragma unroll
            for (int mt = 0; mt < 4; mt++)
#pragma unroll
                for (int ntp = 0; ntp < 4; ntp++) {
                    mma_bf16(acc[mt][2 * ntp],     a[mt], &b[ntp][0]);
                    mma_bf16(acc[mt][2 * ntp + 1], a[mt], &b[ntp][2]);
                }
        }
        CP_COMMIT();                     // one group per chunk (possibly empty)
    }

    // epilogue: fold bias, .cs-stream bf16 scores, per-row tile max sidecar
    float bc0[8], bc1[8];
#pragma unroll
    for (int nt = 0; nt < 8; nt++) {
        int c = col0 + wn * 64 + nt * 8 + q * 2;
        bc0[nt] = __ldg(&g_bias[c]);
        bc1[nt] = __ldg(&g_bias[c + 1]);
    }
#pragma unroll
    for (int mt = 0; mt < 4; mt++) {
        int r = row0 + wm * 64 + mt * 16 + g;
        float m1 = -CUDART_INF_F, m2 = -CUDART_INF_F;
#pragma unroll
        for (int nt = 0; nt < 8; nt++) {
            float v0 = acc[mt][nt][0] + bc0[nt];
            float v1 = acc[mt][nt][1] + bc1[nt];
            float v2 = acc[mt][nt][2] + bc0[nt];
            float v3 = acc[mt][nt][3] + bc1[nt];
            m1 = fmaxf(m1, fmaxf(v0, v1));
            m2 = fmaxf(m2, fmaxf(v2, v3));
            int c2 = (col0 >> 1) + wn * 32 + nt * 4 + q;
            __stcs(&g_sc2[(size_t)r * (K_CODES / 2) + c2], pack_bf2(v0, v1));
            __stcs(&g_sc2[(size_t)(r + 8) * (K_CODES / 2) + c2], pack_bf2(v2, v3));
        }
        m1 = fmaxf(m1, __shfl_xor_sync(0xFFFFFFFFu, m1, 1));
        m1 = fmaxf(m1, __shfl_xor_sync(0xFFFFFFFFu, m1, 2));
        m2 = fmaxf(m2, __shfl_xor_sync(0xFFFFFFFFu, m2, 1));
        m2 = fmaxf(m2, __shfl_xor_sync(0xFFFFFFFFu, m2, 2));
        if (q == 0) {
            atomicMax(&g_tilemax[(size_t)r * NTILE + blockIdx.x], fenc(m1));
            atomicMax(&g_tilemax[(size_t)(r + 8) * NTILE + blockIdx.x], fenc(m2));
        }
    }
}

// ---------------------------------------------------------------------------
// Select + gather: warp per row. tilemax -> ballot tiles -> candidate filter
// -> (n==1 shortcut) -> exact fp32 rescore (x loaded lazily) -> output.
// ---------------------------------------------------------------------------
__global__ __launch_bounds__(256) void select_kernel(const float* __restrict__ x,
                                                     const float* __restrict__ embed,
                                                     float* __restrict__ out, int write_ind) {
    __shared__ int cnt[8];
    __shared__ int cands[8][MAXCAND];

    const int wrow = threadIdx.x >> 5;
    const int row = blockIdx.x * 8 + wrow;
    const int lane = threadIdx.x & 31;
    if (row >= N_ROWS) return;

    const uint32_t tenc = g_tilemax[(size_t)row * NTILE + lane];

    if (lane == 0) cnt[wrow] = 0;
    __syncwarp();

    const float4* x4 = reinterpret_cast<const float4*>(x + (size_t)row * DDIM);

    const float tv = fdec(tenc);
    float gmax = tv;
#pragma unroll
    for (int off = 16; off; off >>= 1) gmax = fmaxf(gmax, __shfl_xor_sync(0xFFFFFFFFu, gmax, off));

    const float margin = 0.02f * g_xnorm[row] * sqrtf(__int_as_float(g_emax2)) + 1.0f;
    const float thr = gmax - margin;

    unsigned tmask = __ballot_sync(0xFFFFFFFFu, tv >= thr);

    const uint4* s16 = reinterpret_cast<const uint4*>(g_sc2 + (size_t)row * (K_CODES / 2));

    while (tmask) {
        const int t = __ffs(tmask) - 1;
        tmask &= tmask - 1;
        uint4 u = s16[t * 32 + lane];
#pragma unroll
        for (int w = 0; w < 4; w++) {
            uint32_t uw = (&u.x)[w];
            float2 p = __bfloat1622float2(*reinterpret_cast<__nv_bfloat162*>(&uw));
            if (p.x >= thr) {
                int pos = atomicAdd(&cnt[wrow], 1);
                if (pos < MAXCAND) cands[wrow][pos] = t * 256 + lane * 8 + w * 2;
            }
            if (p.y >= thr) {
                int pos = atomicAdd(&cnt[wrow], 1);
                if (pos < MAXCAND) cands[wrow][pos] = t * 256 + lane * 8 + w * 2 + 1;
            }
        }
    }
    __syncwarp();
    const int n = cnt[wrow];

    float best = -CUDART_INF_F;
    int bi = K_CODES;

    if (n == 1) {
        bi = cands[wrow][0];             // sole survivor of a superset filter
    } else if (n <= MAXCAND) {
        float4 xv[4];
#pragma unroll
        for (int j = 0; j < 4; j++) xv[j] = x4[lane + 32 * j];
        for (int ci = 0; ci < n; ci++) {
            int k = cands[wrow][ci];
            const float4* e4 = reinterpret_cast<const float4*>(embed + (size_t)k * DDIM);
            float s = 0.f;
#pragma unroll
            for (int j = 0; j < 4; j++) {
                float4 ev = e4[lane + 32 * j];
                s += xv[j].x * ev.x + xv[j].y * ev.y + xv[j].z * ev.z + xv[j].w * ev.w;
            }
#pragma unroll
            for (int off = 16; off; off >>= 1) s += __shfl_xor_sync(0xFFFFFFFFu, s, off);
            float v = s + g_bias[k];
            if (v > best || (v == best && k < bi)) { best = v; bi = k; }
        }
    } else {
        for (int k = lane; k < K_CODES; k += 32) {
            const float4* e4 = reinterpret_cast<const float4*>(embed + (size_t)k * DDIM);
            float s = 0.f;
            for (int j = 0; j < DDIM / 4; j++) {
                float4 ev = e4[j];
                float4 xw = x4[j];
                s += xw.x * ev.x + xw.y * ev.y + xw.z * ev.z + xw.w * ev.w;
            }
            float v = s + g_bias[k];
            if (v > best || (v == best && k < bi)) { best = v; bi = k; }
        }
#pragma unroll
        for (int off = 16; off; off >>= 1) {
            float ov = __shfl_xor_sync(0xFFFFFFFFu, best, off);
            int   oi = __shfl_xor_sync(0xFFFFFFFFu, bi, off);
            if (ov > best || (ov == best && oi < bi)) { best = ov; bi = oi; }
        }
    }

    bi = __shfl_sync(0xFFFFFFFFu, bi, 0);

    const float4* src = reinterpret_cast<const float4*>(embed + (size_t)bi * DDIM);
    float4* dst = reinterpret_cast<float4*>(out + (size_t)row * DDIM);
#pragma unroll
    for (int j = 0; j < 4; j++) dst[lane + 32 * j] = src[lane + 32 * j];
    if (write_ind && lane == 0) out[(size_t)N_ROWS * DDIM + row] = (float)bi;
}

// ---------------------------------------------------------------------------
extern "C" void kernel_launch(void* const* d_in, const int* in_sizes, int n_in,
                              void* d_out, int out_size) {
    const float* x     = (const float*)d_in[0];
    const float* embed = (const float*)d_in[1];
    float* out = (float*)d_out;
    (void)in_sizes; (void)n_in;
    int write_ind = (out_size >= N_ROWS * DDIM + N_ROWS) ? 1 : 0;

    cudaFuncSetAttribute(gemm_kernel, cudaFuncAttributeMaxDynamicSharedMemorySize, SMEM_GEMM);

    conv_kernel<<<(N_ROWS + K_CODES) / 8, 256>>>(x, embed);
    gemm_kernel<<<dim3(K_CODES / BN, N_ROWS / BM), 256, SMEM_GEMM>>>();
    select_kernel<<<N_ROWS / 8, 256>>>(x, embed, out, write_ind);
}